// round 4
// baseline (speedup 1.0000x reference)
#include <cuda_runtime.h>
#include <math.h>

#define BB 8
#define CC 256
#define HH 128
#define WW 128
#define NN (HH*WW)          // 16384
#define NPOS 256
#define NHARD 96
#define NRAND 32
#define TEMP_INV (1.0f/0.07f)

#define DSTR 260            // padded row stride (floats), 16B aligned, quad-stride 65 (odd)
#define NB_MAIN (BB*NN/32)  // 4096
#define NB_HARD (BB*NPOS)   // 2048

typedef unsigned long long u64;

__device__ __forceinline__ u64 fma2(u64 a, u64 b, u64 c) {
    u64 d;
    asm("fma.rn.f32x2 %0,%1,%2,%3;" : "=l"(d) : "l"(a), "l"(b), "l"(c));
    return d;
}
__device__ __forceinline__ float2 unpack2(u64 v) {
    float2 f;
    asm("mov.b64 {%0,%1},%2;" : "=f"(f.x), "=f"(f.y) : "l"(v));
    return f;
}

// ---------------- scratch (static device globals; no allocation) ------------
__device__ float g_rgbT[BB*NN*CC];      // normalized rgb, [b][pixel][channel]
__device__ float g_pos[BB*NN];
__device__ float g_lse[BB*NN];
__device__ float g_maxneg[BB*NN];
__device__ float g_lse_hard[BB*NPOS];
__device__ float g_max_hard[BB*NPOS];
__device__ float g_acc[3];              // loss_sum, mask_sum, correct_sum

// ---------------- kernel 1: normalize + transpose rgb -> g_rgbT --------------
__global__ __launch_bounds__(256) void k_norm_t(const float* __restrict__ in) {
    __shared__ float s_tile[CC*33];
    __shared__ float s_red[8*33];
    __shared__ float s_inv[32];
    const int tid = threadIdx.x;
    const int tx = tid & 31;        // pixel in tile
    const int ty = tid >> 5;        // channel group
    const int blocksPerBatch = NN/32;
    const int b  = blockIdx.x / blocksPerBatch;
    const int n0 = (blockIdx.x % blocksPerBatch) * 32;

    if (blockIdx.x == 0 && tid < 3) g_acc[tid] = 0.0f;

    const float* src = in + b*CC*NN + n0;
    #pragma unroll 8
    for (int i = 0; i < 32; i++) {
        int c = i*8 + ty;
        s_tile[c*33 + tx] = src[c*NN + tx];
    }
    __syncthreads();

    float ss = 0.0f;
    #pragma unroll
    for (int j = 0; j < 32; j++) {
        float v = s_tile[(ty*32 + j)*33 + tx];
        ss += v*v;
    }
    s_red[ty*33 + tx] = ss;
    __syncthreads();
    if (ty == 0) {
        float t = 0.0f;
        #pragma unroll
        for (int j = 0; j < 8; j++) t += s_red[j*33 + tx];
        s_inv[tx] = 1.0f / fmaxf(sqrtf(t), 1e-12f);
    }
    __syncthreads();

    float* dst = g_rgbT + (b*NN + n0)*CC;
    const int cb = tid & 63;
    const int pq = tid >> 6;
    #pragma unroll
    for (int it = 0; it < 8; it++) {
        int px = it*4 + pq;
        float inv = s_inv[px];
        float4 v;
        v.x = s_tile[(cb*4+0)*33 + px] * inv;
        v.y = s_tile[(cb*4+1)*33 + px] * inv;
        v.z = s_tile[(cb*4+2)*33 + px] * inv;
        v.w = s_tile[(cb*4+3)*33 + px] * inv;
        reinterpret_cast<float4*>(dst + px*CC)[cb] = v;
    }
}

// ---------------- kernel 2: fused main (32px tiles) + hard blocks ------------
__device__ __forceinline__ int corner_idx(int xx, int yy, float& w) {
    bool v = (xx >= 0) & (xx < WW) & (yy >= 0) & (yy < HH);
    if (!v) w = 0.0f;
    int cx = min(max(xx, 0), WW-1);
    int cy = min(max(yy, 0), HH-1);
    return cy*WW + cx;
}

__global__ __launch_bounds__(256, 2) void k_fused(const float* __restrict__ dep,
                                                  const float* __restrict__ proj,
                                                  const int*   __restrict__ rand_idx,
                                                  const int*   __restrict__ offu,
                                                  const int*   __restrict__ offv) {
    extern __shared__ float sm[];
    const int tid = threadIdx.x;
    const int tx  = tid & 31;
    const int ty  = tid >> 5;

    if (blockIdx.x >= NB_MAIN) {
        // ================= HARD-NEGATIVE BLOCK =================
        float* s_depv = sm;              // 256
        float* s_hsim = sm + CC;         // 96
        float* s_red2 = s_hsim + NHARD;  // 8
        float* s_invd = s_red2 + 8;      // 1
        const int hb = blockIdx.x - NB_MAIN;
        const int b = hb >> 8;
        const int p = hb & 255;
        const int gh = (p >> 4) * 8;
        const int gw = (p & 15) * 8;
        const int ng = gh*WW + gw;

        float v = dep[b*CC*NN + tid*NN + ng];
        {
            float ss = v*v;
            #pragma unroll
            for (int o = 16; o; o >>= 1) ss += __shfl_xor_sync(0xffffffffu, ss, o);
            if (tx == 0) s_red2[ty] = ss;
        }
        __syncthreads();
        if (tid == 0) {
            float t = 0.0f;
            #pragma unroll
            for (int j = 0; j < 8; j++) t += s_red2[j];
            s_invd[0] = TEMP_INV / fmaxf(sqrtf(t), 1e-12f);
        }
        __syncthreads();
        s_depv[tid] = v * s_invd[0];
        __syncthreads();

        float pu = proj[b*2*NN + ng];
        float pv = proj[b*2*NN + NN + ng];
        int posu = (int)fminf(fmaxf(pu, 0.0f), (float)(WW-1));
        int posv = (int)fminf(fmaxf(pv, 0.0f), (float)(HH-1));

        const float4* dv = reinterpret_cast<const float4*>(s_depv);
        #pragma unroll
        for (int g3 = 0; g3 < 3; g3++) {
            int hbase = ty*12 + g3*4;
            const float4* r[4];
            #pragma unroll
            for (int j = 0; j < 4; j++) {
                int h = hbase + j;
                int ou = offu[(b*NHARD + h)*NPOS + p];
                int ov = offv[(b*NHARD + h)*NPOS + p];
                if (ou == 0 && ov == 0) ou = 1;
                int hu = min(max(posu + ou, 0), WW-1);
                int hv = min(max(posv + ov, 0), HH-1);
                r[j] = reinterpret_cast<const float4*>(g_rgbT + (b*NN + hv*WW + hu)*CC);
            }
            float a0 = 0.f, a1 = 0.f, a2 = 0.f, a3 = 0.f;
            #pragma unroll
            for (int jj = 0; jj < 2; jj++) {
                int c4 = jj*32 + tx;
                float4 d = dv[c4];
                float4 v0 = r[0][c4];
                float4 v1 = r[1][c4];
                float4 v2 = r[2][c4];
                float4 v3 = r[3][c4];
                a0 += d.x*v0.x; a0 += d.y*v0.y; a0 += d.z*v0.z; a0 += d.w*v0.w;
                a1 += d.x*v1.x; a1 += d.y*v1.y; a1 += d.z*v1.z; a1 += d.w*v1.w;
                a2 += d.x*v2.x; a2 += d.y*v2.y; a2 += d.z*v2.z; a2 += d.w*v2.w;
                a3 += d.x*v3.x; a3 += d.y*v3.y; a3 += d.z*v3.z; a3 += d.w*v3.w;
            }
            #pragma unroll
            for (int o = 16; o; o >>= 1) {
                a0 += __shfl_xor_sync(0xffffffffu, a0, o);
                a1 += __shfl_xor_sync(0xffffffffu, a1, o);
                a2 += __shfl_xor_sync(0xffffffffu, a2, o);
                a3 += __shfl_xor_sync(0xffffffffu, a3, o);
            }
            if (tx == 0) {
                s_hsim[hbase+0] = a0;
                s_hsim[hbase+1] = a1;
                s_hsim[hbase+2] = a2;
                s_hsim[hbase+3] = a3;
            }
        }
        __syncthreads();

        if (tid < 32) {
            float v0 = s_hsim[tx];
            float v1 = s_hsim[tx + 32];
            float v2 = s_hsim[tx + 64];
            float m = fmaxf(fmaxf(v0, v1), v2);
            #pragma unroll
            for (int o = 16; o; o >>= 1) m = fmaxf(m, __shfl_xor_sync(0xffffffffu, m, o));
            float se = expf(v0 - m) + expf(v1 - m) + expf(v2 - m);
            #pragma unroll
            for (int o = 16; o; o >>= 1) se += __shfl_xor_sync(0xffffffffu, se, o);
            if (tx == 0) {
                g_lse_hard[b*NPOS + p] = m + logf(se);
                g_max_hard[b*NPOS + p] = m;
            }
        }
        return;
    }

    // ================= MAIN BLOCK (32 pixels) =================
    float* s_dep2 = sm;                        // 32 * 260, pixel-major
    float* s_rand = s_dep2 + 32*DSTR;          // 32 * 260
    float* s_sim  = s_rand + NRAND*DSTR;       // 32 * 33
    float* s_pos  = s_sim + NRAND*33;          // 32
    float* s_inv  = s_pos + 32;                // 32
    float* s_red  = s_inv + 32;                // 8 * 33

    const int blocksPerBatch = NN/32;
    const int b  = blockIdx.x / blocksPerBatch;
    const int n0 = (blockIdx.x % blocksPerBatch) * 32;

    // ---- stage dep tile pixel-major + partial norms ----
    {
        const int px = tx;                     // pixel 0..31
        const int cg = ty;                     // channel group 0..7
        const float* dsrc = dep + b*CC*NN + n0 + px;
        float ss = 0.0f;
        #pragma unroll 8
        for (int i = 0; i < 32; i++) {
            int c = i*8 + cg;
            float v = dsrc[c*NN];
            s_dep2[px*DSTR + c] = v;
            ss += v*v;
        }
        s_red[cg*33 + px] = ss;
    }
    // ---- stage rand vectors ----
    {
        int k = tid >> 3, part = tid & 7;
        int ridx = rand_idx[b*NRAND + k];
        const float4* row = reinterpret_cast<const float4*>(g_rgbT + (b*NN + ridx)*CC);
        float4* dstr = reinterpret_cast<float4*>(s_rand + k*DSTR);
        #pragma unroll
        for (int i = 0; i < 8; i++) dstr[part + 8*i] = row[part + 8*i];
    }
    __syncthreads();
    if (tid < 32) {
        float t = 0.0f;
        #pragma unroll
        for (int j = 0; j < 8; j++) t += s_red[j*33 + tid];
        s_inv[tid] = 1.0f / fmaxf(sqrtf(t), 1e-12f);
    }
    __syncthreads();

    // ---- phase 2: pos_sim (warp handles 4 pixels) ----
    const float* projU = proj + b*2*NN;
    const float* projV = projU + NN;
    const float4* dv4 = reinterpret_cast<const float4*>(s_dep2);
    #pragma unroll
    for (int q = 0; q < 4; q++) {
        int px = ty*4 + q;
        int n  = n0 + px;
        float pu = projU[n], pv = projV[n];
        float x0f = floorf(pu), y0f = floorf(pv);
        float wx = pu - x0f, wy = pv - y0f;
        int x0 = (int)x0f, y0 = (int)y0f;
        float w00 = (1.0f-wx)*(1.0f-wy), w10 = wx*(1.0f-wy);
        float w01 = (1.0f-wx)*wy,        w11 = wx*wy;
        int i00 = corner_idx(x0,   y0,   w00);
        int i10 = corner_idx(x0+1, y0,   w10);
        int i01 = corner_idx(x0,   y0+1, w01);
        int i11 = corner_idx(x0+1, y0+1, w11);
        const float4* r00 = reinterpret_cast<const float4*>(g_rgbT + (b*NN + i00)*CC);
        const float4* r10 = reinterpret_cast<const float4*>(g_rgbT + (b*NN + i10)*CC);
        const float4* r01 = reinterpret_cast<const float4*>(g_rgbT + (b*NN + i01)*CC);
        const float4* r11 = reinterpret_cast<const float4*>(g_rgbT + (b*NN + i11)*CC);
        float pacc = 0.0f;
        #pragma unroll
        for (int jj = 0; jj < 2; jj++) {
            int c4 = tx + jj*32;
            float4 d  = dv4[px*(DSTR/4) + c4];
            float4 a00 = r00[c4], a10 = r10[c4], a01 = r01[c4], a11 = r11[c4];
            pacc += d.x*(w00*a00.x + w10*a10.x + w01*a01.x + w11*a11.x);
            pacc += d.y*(w00*a00.y + w10*a10.y + w01*a01.y + w11*a11.y);
            pacc += d.z*(w00*a00.z + w10*a10.z + w01*a01.z + w11*a11.z);
            pacc += d.w*(w00*a00.w + w10*a10.w + w01*a01.w + w11*a11.w);
        }
        #pragma unroll
        for (int o = 16; o; o >>= 1) pacc += __shfl_xor_sync(0xffffffffu, pacc, o);
        if (tx == 0) s_pos[px] = pacc;
    }

    // ---- phase 3: rand dots. lane = (pixel, k-group). Warp owns 4 pixels. ----
    // px = ty*4 + (lane>>3), k = (lane&7) + 8*kk, kk 0..3.
    {
        const int px    = ty*4 + (tx >> 3);
        const int kbase = tx & 7;
        const ulonglong2* dp = reinterpret_cast<const ulonglong2*>(s_dep2 + px*DSTR);
        const ulonglong2* rp0 = reinterpret_cast<const ulonglong2*>(s_rand + (kbase +  0)*DSTR);
        const ulonglong2* rp1 = reinterpret_cast<const ulonglong2*>(s_rand + (kbase +  8)*DSTR);
        const ulonglong2* rp2 = reinterpret_cast<const ulonglong2*>(s_rand + (kbase + 16)*DSTR);
        const ulonglong2* rp3 = reinterpret_cast<const ulonglong2*>(s_rand + (kbase + 24)*DSTR);
        u64 a0=0, a1=0, a2=0, a3=0;
        #pragma unroll 8
        for (int c4 = 0; c4 < 64; c4++) {
            ulonglong2 d = dp[c4];
            ulonglong2 r0 = rp0[c4], r1 = rp1[c4], r2 = rp2[c4], r3 = rp3[c4];
            a0 = fma2(d.x, r0.x, a0); a0 = fma2(d.y, r0.y, a0);
            a1 = fma2(d.x, r1.x, a1); a1 = fma2(d.y, r1.y, a1);
            a2 = fma2(d.x, r2.x, a2); a2 = fma2(d.y, r2.y, a2);
            a3 = fma2(d.x, r3.x, a3); a3 = fma2(d.y, r3.y, a3);
        }
        float2 f;
        f = unpack2(a0); s_sim[(kbase +  0)*33 + px] = f.x + f.y;
        f = unpack2(a1); s_sim[(kbase +  8)*33 + px] = f.x + f.y;
        f = unpack2(a2); s_sim[(kbase + 16)*33 + px] = f.x + f.y;
        f = unpack2(a3); s_sim[(kbase + 24)*33 + px] = f.x + f.y;
    }
    __syncthreads();

    // ---- phase 4: per-pixel logsumexp / max, lane-parallel over negatives ----
    #pragma unroll
    for (int q = 0; q < 4; q++) {
        int px = ty*4 + q;
        float scale = s_inv[px] * TEMP_INV;
        float pos = s_pos[px] * scale;
        float v = s_sim[tx*33 + px] * scale;
        float mneg = v;
        #pragma unroll
        for (int o = 16; o; o >>= 1) mneg = fmaxf(mneg, __shfl_xor_sync(0xffffffffu, mneg, o));
        float m = fmaxf(pos, mneg);
        float e = expf(v - m);
        #pragma unroll
        for (int o = 16; o; o >>= 1) e += __shfl_xor_sync(0xffffffffu, e, o);
        if (tx == 0) {
            int gp = b*NN + n0 + px;
            g_pos[gp]    = pos;
            g_lse[gp]    = m + logf(e + expf(pos - m));
            g_maxneg[gp] = mneg;
        }
    }
}

// ---------------- kernel 4: loss/accuracy reduction ---------------------------
__global__ __launch_bounds__(256) void k_loss(const float* __restrict__ valid) {
    __shared__ float sA[8], sB[8], sC[8];
    const int g = blockIdx.x * 256 + threadIdx.x;
    const int b = g >> 14;
    const int n = g & (NN-1);
    const int vq = n >> 7;
    const int u  = n & 127;

    float lse = g_lse[g];
    float pos = g_pos[g];
    float mx  = g_maxneg[g];
    if (((vq & 7) == 0) && ((u & 7) == 0)) {
        int p = (vq >> 3) * 16 + (u >> 3);
        float lh = g_lse_hard[b*NPOS + p];
        float mh = g_max_hard[b*NPOS + p];
        float m = fmaxf(lse, lh);
        lse = m + logf(expf(lse - m) + expf(lh - m));
        mx = fmaxf(mx, mh);
    }
    float mask = valid[g];
    float lossp = (lse - pos) * mask;
    float corr = (pos > mx && mask > 0.5f) ? 1.0f : 0.0f;
    float mk = mask;

    #pragma unroll
    for (int o = 16; o; o >>= 1) {
        lossp += __shfl_xor_sync(0xffffffffu, lossp, o);
        mk    += __shfl_xor_sync(0xffffffffu, mk,    o);
        corr  += __shfl_xor_sync(0xffffffffu, corr,  o);
    }
    if ((threadIdx.x & 31) == 0) {
        sA[threadIdx.x >> 5] = lossp;
        sB[threadIdx.x >> 5] = mk;
        sC[threadIdx.x >> 5] = corr;
    }
    __syncthreads();
    if (threadIdx.x == 0) {
        float a = 0.f, bb2 = 0.f, c2 = 0.f;
        #pragma unroll
        for (int j = 0; j < 8; j++) { a += sA[j]; bb2 += sB[j]; c2 += sC[j]; }
        atomicAdd(&g_acc[0], a);
        atomicAdd(&g_acc[1], bb2);
        atomicAdd(&g_acc[2], c2);
    }
}

// ---------------- kernel 5: epilogue ------------------------------------------
__global__ void k_out(float* out) {
    float denom = fmaxf(g_acc[1], 1.0f);
    out[0] = g_acc[0] / denom;
    out[1] = g_acc[2] / denom * 100.0f;
}

// ---------------- launch -------------------------------------------------------
extern "C" void kernel_launch(void* const* d_in, const int* in_sizes, int n_in,
                              void* d_out, int out_size) {
    const float* rgb   = (const float*)d_in[0];
    const float* dep   = (const float*)d_in[1];
    const float* proj  = (const float*)d_in[2];
    const float* valid = (const float*)d_in[3];
    const int*   ridx  = (const int*)d_in[4];
    const int*   offu  = (const int*)d_in[5];
    const int*   offv  = (const int*)d_in[6];
    float* out = (float*)d_out;

    const int smem_fused = (32*DSTR + NRAND*DSTR + NRAND*33 + 32 + 32 + 8*33) * (int)sizeof(float);
    cudaFuncSetAttribute(k_fused, cudaFuncAttributeMaxDynamicSharedMemorySize, smem_fused);

    k_norm_t<<<BB*NN/32, 256>>>(rgb);
    k_fused<<<NB_MAIN + NB_HARD, 256, smem_fused>>>(dep, proj, ridx, offu, offv);
    k_loss<<<BB*NN/256, 256>>>(valid);
    k_out<<<1, 1>>>(out);
}